// round 6
// baseline (speedup 1.0000x reference)
#include <cuda_runtime.h>
#include <cstdint>

#define Bn 32
#define Hn 56
#define Wn 56
#define Cn 256
#define RS (Wn * Cn)

typedef unsigned long long ull;
typedef unsigned int u32;

// ---- packed f32x2 helpers (Blackwell FFMA2 path: only reachable via PTX) ----
__device__ __forceinline__ ull fma2(ull a, ull b, ull c) {
    ull d; asm("fma.rn.f32x2 %0, %1, %2, %3;" : "=l"(d) : "l"(a), "l"(b), "l"(c)); return d;
}
__device__ __forceinline__ ull mul2(ull a, ull b) {
    ull d; asm("mul.rn.f32x2 %0, %1, %2;" : "=l"(d) : "l"(a), "l"(b)); return d;
}
__device__ __forceinline__ ull add2(ull a, ull b) {
    ull d; asm("add.rn.f32x2 %0, %1, %2;" : "=l"(d) : "l"(a), "l"(b)); return d;
}
__device__ __forceinline__ ull pk2(u32 lo, u32 hi) {
    ull d; asm("mov.b64 %0, {%1, %2};" : "=l"(d) : "r"(lo), "r"(hi)); return d;
}
__device__ __forceinline__ ull dup2(u32 v) {
    ull d; asm("mov.b64 %0, {%1, %1};" : "=l"(d) : "r"(v)); return d;
}
__device__ __forceinline__ void up2(ull v, u32 &lo, u32 &hi) {
    asm("mov.b64 {%0, %1}, %2;" : "=r"(lo), "=r"(hi) : "l"(v));
}
// volatile LDS.64 — forces a fresh shared load each use (no re-hoist to regs)
__device__ __forceinline__ ull lds64(u32 addr) {
    ull d; asm volatile("ld.shared.b64 %0, [%1];" : "=l"(d) : "r"(addr)); return d;
}
__device__ __forceinline__ u32 smem_u32(const void* p) {
    u32 a; asm("{ .reg .u64 t; cvta.to.shared.u64 t, %1; cvt.u32.u64 %0, t; }"
               : "=r"(a) : "l"(p));
    return a;
}

__global__ void __launch_bounds__(128, 6) gdn_kernel(
    const float* __restrict__ x,  const float* __restrict__ gk,
    const float* __restrict__ gs, const float* __restrict__ beta,
    const float* __restrict__ bo, const float* __restrict__ go,
    float* __restrict__ out)
{
    __shared__ ull staps[8][128];    // Ps taps, [tap][thread] -> conflict-free LDS.64

    const int ct  = threadIdx.x;     // channel-thread: channels [2ct, 2ct+2)
    const int cb  = ct * 2;
    const int qid = ct & 3;          // position within 4-thread group quad

    int bi = blockIdx.x;
    const int wp = bi % 28; bi /= 28;   // w-pair: output cols w0, w0+1
    const int hq = bi & 3;  bi >>= 2;
    const int b  = bi;
    const int w0 = wp * 2;
    const int h0 = hq * 14;
    const bool wl = (wp > 0), wr = (wp < 27);

    // ---- Ps taps (3x3 minus center) -> smem ----
    const int tapi[8] = {0, 1, 2, 3, 5, 6, 7, 8};
#pragma unroll
    for (int t = 0; t < 8; t++)
        staps[t][ct] = *(const ull*)(gs + tapi[t] * Cn + cb);
    const u32 tbase = smem_u32(&staps[0][ct]);
    __syncthreads();

    // ---- Pk weights, pre-permuted into shuffle-delivery order (registers) ----
    ull Wp[8];
#pragma unroll
    for (int j = 0; j < 4; j++) {
        const int src = qid ^ j;
        Wp[2 * j]     = *(const ull*)(gk + (2 * src)     * Cn + cb);
        Wp[2 * j + 1] = *(const ull*)(gk + (2 * src + 1) * Cn + cb);
    }

    float2 bt = *(const float2*)(beta + cb);
    const ull bp  = pk2(__float_as_uint(bt.x + 1e-6f), __float_as_uint(bt.y + 1e-6f));
    const ull gov = *(const ull*)(go + cb);
    const ull bov = *(const ull*)(bo + cb);

    const float* xw = x   + (((size_t)b * Hn) * Wn + w0) * Cn + cb;
    float*       ob = out + (((size_t)b * Hn) * Wn + w0) * Cn + cb;

    // load 4 raw columns (w0-1, w0, w0+1, w0+2) of row hg
    auto ldrow = [&](int hg, ull &L, ull &C0, ull &C1, ull &R) {
        L = 0; C0 = 0; C1 = 0; R = 0;
        if (hg >= 0 && hg < Hn) {
            const float* p = xw + (size_t)hg * RS;
            if (wl) L = *(const ull*)(p - Cn);
            C0 = *(const ull*)(p);
            C1 = *(const ull*)(p + Cn);
            if (wr) R = *(const ull*)(p + 2 * Cn);
        }
    };

    // squared window rows a(h-1), b(h), c(h+1) x cols (w0-1, w0, w0+1, w0+2)
    ull aSL, aS0, aS1, aSR, bSL, bS0, bS1, bSR, cSL, cS0, cS1, cSR;
    ull rb0, rb1, rc0, rc1;          // raw center cols for rows h (out) and h+1
    ull p1L, p1C0, p1C1, p1R;        // raw prefetch row h+2
    ull p2L, p2C0, p2C1, p2R;        // raw prefetch row h+3

    {
        ull L, C0, C1, R;
        ldrow(h0 - 1, L, C0, C1, R);
        aSL = mul2(L, L); aS0 = mul2(C0, C0); aS1 = mul2(C1, C1); aSR = mul2(R, R);
        ldrow(h0, L, C0, C1, R);
        bSL = mul2(L, L); bS0 = mul2(C0, C0); bS1 = mul2(C1, C1); bSR = mul2(R, R);
        rb0 = C0; rb1 = C1;
        ldrow(h0 + 1, L, C0, C1, R);
        cSL = mul2(L, L); cS0 = mul2(C0, C0); cS1 = mul2(C1, C1); cSR = mul2(R, R);
        rc0 = C0; rc1 = C1;
        ldrow(h0 + 2, p1L, p1C0, p1C1, p1R);
        ldrow(h0 + 3, p2L, p2C0, p2C1, p2R);
    }

#pragma unroll
    for (int s = 0; s < 14; s++) {
        const int h = h0 + s;

        // ---- Pk inputs: independent butterflies off both center x^2 cols ----
        const ull v0b = __shfl_xor_sync(0xffffffffu, bS0, 1);
        const ull v0c = __shfl_xor_sync(0xffffffffu, bS0, 2);
        const ull v0d = __shfl_xor_sync(0xffffffffu, bS0, 3);
        const ull v1b = __shfl_xor_sync(0xffffffffu, bS1, 1);
        const ull v1c = __shfl_xor_sync(0xffffffffu, bS1, 2);
        const ull v1d = __shfl_xor_sync(0xffffffffu, bS1, 3);

        // ---- Ps taps from smem (once per step, reused by both cols) ----
        const ull k0 = lds64(tbase + 0 * 1024);
        const ull k1 = lds64(tbase + 1 * 1024);
        const ull k2 = lds64(tbase + 2 * 1024);
        const ull k3 = lds64(tbase + 3 * 1024);
        const ull k4 = lds64(tbase + 4 * 1024);
        const ull k5 = lds64(tbase + 5 * 1024);
        const ull k6 = lds64(tbase + 6 * 1024);
        const ull k7 = lds64(tbase + 7 * 1024);

        u32 s0, s1;
        // ---- col w0: Pk (2 chains) ----
        ull A0 = bp, B0;
        up2(bS0, s0, s1);
        A0 = fma2(dup2(s0), Wp[0], A0);  B0 = mul2(dup2(s1), Wp[1]);
        up2(v0b, s0, s1);
        A0 = fma2(dup2(s0), Wp[2], A0);  B0 = fma2(dup2(s1), Wp[3], B0);
        up2(v0c, s0, s1);
        A0 = fma2(dup2(s0), Wp[4], A0);  B0 = fma2(dup2(s1), Wp[5], B0);
        up2(v0d, s0, s1);
        A0 = fma2(dup2(s0), Wp[6], A0);  B0 = fma2(dup2(s1), Wp[7], B0);
        // ---- col w0: Ps (2 chains) ----
        ull C0a = mul2(aSL, k0);
        ull D0a = mul2(aS0, k1);
        C0a = fma2(aS1, k2, C0a);
        D0a = fma2(bSL, k3, D0a);
        C0a = fma2(bS1, k4, C0a);
        D0a = fma2(cSL, k5, D0a);
        C0a = fma2(cS0, k6, C0a);
        D0a = fma2(cS1, k7, D0a);
        const ull acc0 = add2(add2(A0, B0), add2(C0a, D0a));

        // ---- col w0+1: Pk ----
        ull A1 = bp, B1;
        up2(bS1, s0, s1);
        A1 = fma2(dup2(s0), Wp[0], A1);  B1 = mul2(dup2(s1), Wp[1]);
        up2(v1b, s0, s1);
        A1 = fma2(dup2(s0), Wp[2], A1);  B1 = fma2(dup2(s1), Wp[3], B1);
        up2(v1c, s0, s1);
        A1 = fma2(dup2(s0), Wp[4], A1);  B1 = fma2(dup2(s1), Wp[5], B1);
        up2(v1d, s0, s1);
        A1 = fma2(dup2(s0), Wp[6], A1);  B1 = fma2(dup2(s1), Wp[7], B1);
        // ---- col w0+1: Ps ----
        ull C1a = mul2(aS0, k0);
        ull D1a = mul2(aS1, k1);
        C1a = fma2(aSR, k2, C1a);
        D1a = fma2(bS0, k3, D1a);
        C1a = fma2(bSR, k4, C1a);
        D1a = fma2(cS0, k5, D1a);
        C1a = fma2(cS1, k6, C1a);
        D1a = fma2(cSR, k7, D1a);
        const ull acc1 = add2(add2(A1, B1), add2(C1a, D1a));

        // ---- epilogue: x * rsqrt(acc) * gamma_o + beta_o (both cols) ----
        u32 a0, a1;
        float* po = ob + (size_t)h * RS;
        up2(acc0, a0, a1);
        {
            const float r0 = rsqrtf(__uint_as_float(a0));
            const float r1 = rsqrtf(__uint_as_float(a1));
            const ull rp = pk2(__float_as_uint(r0), __float_as_uint(r1));
            *(ull*)(po) = fma2(mul2(rb0, rp), gov, bov);
        }
        up2(acc1, a0, a1);
        {
            const float r0 = rsqrtf(__uint_as_float(a0));
            const float r1 = rsqrtf(__uint_as_float(a1));
            const ull rp = pk2(__float_as_uint(r0), __float_as_uint(r1));
            *(ull*)(po + Cn) = fma2(mul2(rb1, rp), gov, bov);
        }

        // ---- shift window; absorb prefetch row 1; rotate; issue new load ----
        aSL = bSL; aS0 = bS0; aS1 = bS1; aSR = bSR;
        bSL = cSL; bS0 = cS0; bS1 = cS1; bSR = cSR;
        cSL = mul2(p1L, p1L);  cS0 = mul2(p1C0, p1C0);
        cS1 = mul2(p1C1, p1C1); cSR = mul2(p1R, p1R);
        rb0 = rc0; rb1 = rc1;
        rc0 = p1C0; rc1 = p1C1;
        p1L = p2L; p1C0 = p2C0; p1C1 = p2C1; p1R = p2R;
        ldrow(h + 4, p2L, p2C0, p2C1, p2R);
    }
}

extern "C" void kernel_launch(void* const* d_in, const int* in_sizes, int n_in,
                              void* d_out, int out_size) {
    const float* x    = (const float*)d_in[0];
    const float* gk   = (const float*)d_in[1];
    const float* gs   = (const float*)d_in[2];
    const float* beta = (const float*)d_in[3];
    const float* bo   = (const float*)d_in[4];
    const float* go   = (const float*)d_in[5];
    gdn_kernel<<<Bn * 4 * 28, 128>>>(x, gk, gs, beta, bo, go, (float*)d_out);
}